// round 9
// baseline (speedup 1.0000x reference)
#include <cuda_runtime.h>
#include <cuda_bf16.h>
#include <cstdint>

// ContrastiveLoss B=4096, F=256.
// loss = -mean(pos)/T + [10*sum_offdiag(s) - (2B-1)*sum_i LSE_i]/(4B^2)
// INT8 mma.sync m16n8k32 (q=round(127c), s=i/16129), upper-triangle tiles only,
// sum_offdiag(s) = ||sum_i c_i||^2 - 2B (analytic).
// R9: ex2.approx.f32 via inline PTX (guaranteed single MUFU.EX2); lean normalize.

#define BROWS  4096
#define FDIM   256
#define TBROWS 8192
#define TM     128
#define NTILES 64
#define GRID_S 296
#define GROWB  256
#define SSTR   272
#define TILE_SM (TM * SSTR)            // 34816
#define TILE_GM (TM * GROWB)           // 32768

// ---------------- scratch (zero-init at load; finalize re-zeroes) ----------------
__device__ __align__(16) int8_t g_Cq[TBROWS * FDIM];
__device__ float g_rowE[TBROWS];
__device__ float g_colV[FDIM];
__device__ float g_posPart[512];

__device__ __forceinline__ float ex2_mufu(float x) {
    float r;
    asm("ex2.approx.f32 %0, %1;" : "=f"(r) : "f"(x));
    return r;
}

// ================= kernel 1: normalize + quantize + pos sim + colsum RED =================
__global__ void __launch_bounds__(256) normalize_kernel(
    const float* __restrict__ x1, const float* __restrict__ x2)
{
    int warp = threadIdx.x >> 5, lane = threadIdx.x & 31;
    int r = blockIdx.x * 8 + warp;
    const float4* a4 = reinterpret_cast<const float4*>(x1 + (size_t)r * FDIM);
    const float4* b4 = reinterpret_cast<const float4*>(x2 + (size_t)r * FDIM);
    float4 a0 = a4[lane], a1 = a4[lane + 32];     // features 4l..4l+3, 128+4l..+3
    float4 b0 = b4[lane], b1 = b4[lane + 32];

    float ss1 = a0.x*a0.x+a0.y*a0.y+a0.z*a0.z+a0.w*a0.w + a1.x*a1.x+a1.y*a1.y+a1.z*a1.z+a1.w*a1.w;
    float ss2 = b0.x*b0.x+b0.y*b0.y+b0.z*b0.z+b0.w*b0.w + b1.x*b1.x+b1.y*b1.y+b1.z*b1.z+b1.w*b1.w;
    float dt  = a0.x*b0.x+a0.y*b0.y+a0.z*b0.z+a0.w*b0.w + a1.x*b1.x+a1.y*b1.y+a1.z*b1.z+a1.w*b1.w;
    #pragma unroll
    for (int o = 16; o > 0; o >>= 1) {
        ss1 += __shfl_xor_sync(~0u, ss1, o);
        ss2 += __shfl_xor_sync(~0u, ss2, o);
        dt  += __shfl_xor_sync(~0u, dt,  o);
    }
    float inv1 = 1.0f / fmaxf(sqrtf(ss1), 1e-7f);
    float inv2 = 1.0f / fmaxf(sqrtf(ss2), 1e-7f);

    float av[8] = {a0.x,a0.y,a0.z,a0.w,a1.x,a1.y,a1.z,a1.w};
    float bv[8] = {b0.x,b0.y,b0.z,b0.w,b1.x,b1.y,b1.z,b1.w};
    int8_t qa[8], qb[8];
    #pragma unroll
    for (int j = 0; j < 8; j++) {
        qa[j] = (int8_t)__float2int_rn(127.f * av[j] * inv1);
        qb[j] = (int8_t)__float2int_rn(127.f * bv[j] * inv2);
    }
    char* o1 = reinterpret_cast<char*>(g_Cq) + (size_t)r * FDIM;
    char* o2 = reinterpret_cast<char*>(g_Cq) + (size_t)(r + BROWS) * FDIM;
    *reinterpret_cast<uint32_t*>(o1 + 4*lane)       = *reinterpret_cast<uint32_t*>(qa);
    *reinterpret_cast<uint32_t*>(o1 + 128 + 4*lane) = *reinterpret_cast<uint32_t*>(qa + 4);
    *reinterpret_cast<uint32_t*>(o2 + 4*lane)       = *reinterpret_cast<uint32_t*>(qb);
    *reinterpret_cast<uint32_t*>(o2 + 128 + 4*lane) = *reinterpret_cast<uint32_t*>(qb + 4);

    // column sums: direct spread-address REDG (all lanes hit distinct features)
    #pragma unroll
    for (int j = 0; j < 4; j++) {
        atomicAdd(&g_colV[4*lane + j],       av[j]   * inv1 + bv[j]   * inv2);
        atomicAdd(&g_colV[128 + 4*lane + j], av[4+j] * inv1 + bv[4+j] * inv2);
    }

    __shared__ float ps[8];
    if (lane == 0) ps[warp] = dt * inv1 * inv2;
    __syncthreads();
    if (threadIdx.x == 0) {
        float s = 0.f;
        #pragma unroll
        for (int i = 0; i < 8; i++) s += ps[i];
        g_posPart[blockIdx.x] = s;
    }
}

// ================= helpers =================
__device__ __forceinline__ uint32_t smem_u32(const void* p) {
    uint32_t a;
    asm("{ .reg .u64 t; cvta.to.shared.u64 t, %1; cvt.u32.u64 %0, t; }" : "=r"(a) : "l"(p));
    return a;
}
#define CP16(dst, src) \
    asm volatile("cp.async.cg.shared.global [%0], [%1], 16;" :: "r"(dst), "l"(src) : "memory")
#define CP_COMMIT() asm volatile("cp.async.commit_group;" ::: "memory")
#define CP_WAIT0()  asm volatile("cp.async.wait_group 0;" ::: "memory")
#define CP_WAIT1()  asm volatile("cp.async.wait_group 1;" ::: "memory")

#define LDM4(R, ADDR) \
    asm volatile("ldmatrix.sync.aligned.m8n8.x4.shared.b16 {%0,%1,%2,%3}, [%4];" \
        : "=r"((R)[0]), "=r"((R)[1]), "=r"((R)[2]), "=r"((R)[3]) : "r"(ADDR))

#define MMAI8(ACC, RA, B0, B1) \
    asm volatile("mma.sync.aligned.m16n8k32.row.col.s32.s8.s8.s32 " \
        "{%0,%1,%2,%3},{%4,%5,%6,%7},{%8,%9},{%0,%1,%2,%3};" \
        : "+r"((ACC)[0]), "+r"((ACC)[1]), "+r"((ACC)[2]), "+r"((ACC)[3]) \
        : "r"((RA)[0]), "r"((RA)[1]), "r"((RA)[2]), "r"((RA)[3]), "r"(B0), "r"(B1))

__device__ __forceinline__ void cp_tile(uint32_t dstBase, const char* src, int tid) {
    #pragma unroll
    for (int i = 0; i < 8; i++) {
        int idx = tid + i * 256;
        int row = idx >> 4, c = idx & 15;
        CP16(dstBase + row * SSTR + c * 16, src + row * GROWB + c * 16);
    }
}
__device__ __forceinline__ void stepPair(int& it, int& jt) {
    if (++jt == NTILES) { ++it; jt = it; }
}

#define SM_A  0
#define SM_B0 TILE_SM
#define SM_B1 (2 * TILE_SM)
#define SM_TOTAL (3 * TILE_SM)    // 104448 -> 2 CTAs/SM

// ================= kernel 2: int8 triangle GEMM + MUFU exp epilogue =================
__global__ void __launch_bounds__(256, 2) sim_kernel() {
    extern __shared__ char smem[];
    const uint32_t sb = smem_u32(smem);
    const int tid = threadIdx.x, warp = tid >> 5, lane = tid & 31;
    const int wm = warp >> 2, wn = warp & 3;
    const int grp = lane >> 2, qid = lane & 3;
    const int b = blockIdx.x;

    const int cnt = 7 + (b < 8);                  // 296*7 + 8 = 2080
    const int p0  = b * 7 + (b < 8 ? b : 8);
    int itC = 0, cum = 0;
    while (cum + (NTILES - itC) <= p0) { cum += NTILES - itC; ++itC; }
    int jtC = itC + (p0 - cum);
    int itN = itC, jtN = jtC;   stepPair(itN, jtN);
    int itN2 = itN, jtN2 = jtN; stepPair(itN2, jtN2);

    const char* gC = reinterpret_cast<const char*>(g_Cq);

    cp_tile(sb + SM_A,  gC + (size_t)itC * TILE_GM, tid);
    cp_tile(sb + SM_B0, gC + (size_t)jtC * TILE_GM, tid);
    CP_COMMIT();
    cp_tile(sb + SM_B1, gC + (size_t)jtN * TILE_GM, tid);
    CP_COMMIT();

    const uint32_t lrow = lane & 15, lhi = (lane >> 4) * 16;
    uint32_t aOff[4], bOff[2];
    #pragma unroll
    for (int mf = 0; mf < 4; mf++) aOff[mf] = sb + SM_A + (wm * 64 + mf * 16 + lrow) * SSTR + lhi;
    #pragma unroll
    for (int h = 0; h < 2; h++)    bOff[h] = (wn * 32 + h * 16 + lrow) * SSTR + lhi;

    bool aFresh = false;
    const float SC = 14.426950408889634f / 16129.0f;   // exp(10*i/127^2) = 2^(i*SC)

    for (int t = 0; t < cnt; t++) {
        if (aFresh) CP_WAIT0(); else CP_WAIT1();
        __syncthreads();
        const uint32_t bB = sb + ((t & 1) ? SM_B1 : SM_B0);

        int acc[4][4][4];
        #pragma unroll
        for (int mf = 0; mf < 4; mf++)
            #pragma unroll
            for (int nf = 0; nf < 4; nf++)
                #pragma unroll
                for (int k = 0; k < 4; k++) acc[mf][nf][k] = 0;

        #pragma unroll
        for (int kk = 0; kk < 8; kk++) {
            uint32_t ra[4][4], rb[2][4];
            #pragma unroll
            for (int mf = 0; mf < 4; mf++) LDM4(ra[mf], aOff[mf] + kk * 32);
            #pragma unroll
            for (int h = 0; h < 2; h++)    LDM4(rb[h], bB + bOff[h] + kk * 32);
            #pragma unroll
            for (int mf = 0; mf < 4; mf++) {
                #pragma unroll
                for (int h = 0; h < 2; h++) {
                    MMAI8(acc[mf][2*h+0], ra[mf], rb[h][0], rb[h][2]);
                    MMAI8(acc[mf][2*h+1], ra[mf], rb[h][1], rb[h][3]);
                }
            }
        }

        // ---- epilogue BEFORE barrier (overlaps other warps' MMA); single MUFU.EX2 per elt ----
        const bool dg = (itC == jtC);
        float rs[8];
        #pragma unroll
        for (int i = 0; i < 8; i++) rs[i] = 0.f;

        if (!dg) {
            float cs[8];
            #pragma unroll
            for (int i = 0; i < 8; i++) cs[i] = 0.f;
            #pragma unroll
            for (int mf = 0; mf < 4; mf++)
                #pragma unroll
                for (int nf = 0; nf < 4; nf++)
                    #pragma unroll
                    for (int k = 0; k < 4; k++) {
                        float e = ex2_mufu((float)acc[mf][nf][k] * SC);
                        rs[mf*2 + (k >> 1)] += e;
                        cs[nf*2 + (k & 1)] += e;
                    }
            #pragma unroll
            for (int i = 0; i < 8; i++) {
                rs[i] += __shfl_xor_sync(~0u, rs[i], 1);
                rs[i] += __shfl_xor_sync(~0u, rs[i], 2);
                cs[i] += __shfl_xor_sync(~0u, cs[i], 4);
                cs[i] += __shfl_xor_sync(~0u, cs[i], 8);
                cs[i] += __shfl_xor_sync(~0u, cs[i], 16);
            }
            if (qid == 0) {
                #pragma unroll
                for (int mf = 0; mf < 4; mf++)
                    #pragma unroll
                    for (int h = 0; h < 2; h++)
                        atomicAdd(&g_rowE[itC*TM + wm*64 + mf*16 + h*8 + grp], rs[mf*2 + h]);
            }
            if (grp == 0) {
                #pragma unroll
                for (int nf = 0; nf < 4; nf++)
                    #pragma unroll
                    for (int par = 0; par < 2; par++)
                        atomicAdd(&g_rowE[jtC*TM + wn*32 + nf*8 + 2*qid + par], cs[nf*2 + par]);
            }
        } else {
            #pragma unroll
            for (int mf = 0; mf < 4; mf++)
                #pragma unroll
                for (int nf = 0; nf < 4; nf++)
                    #pragma unroll
                    for (int k = 0; k < 4; k++) {
                        int rl = wm*64 + mf*16 + grp + (k >> 1)*8;
                        int cl = wn*32 + nf*8 + 2*qid + (k & 1);
                        if (rl != cl) {
                            float e = ex2_mufu((float)acc[mf][nf][k] * SC);
                            rs[mf*2 + (k >> 1)] += e;
                        }
                    }
            #pragma unroll
            for (int i = 0; i < 8; i++) {
                rs[i] += __shfl_xor_sync(~0u, rs[i], 1);
                rs[i] += __shfl_xor_sync(~0u, rs[i], 2);
            }
            if (qid == 0) {
                #pragma unroll
                for (int mf = 0; mf < 4; mf++)
                    #pragma unroll
                    for (int h = 0; h < 2; h++)
                        atomicAdd(&g_rowE[itC*TM + wm*64 + mf*16 + h*8 + grp], rs[mf*2 + h]);
            }
        }

        __syncthreads();                           // all warps done reading smem tiles
        bool nextAFresh = false;
        if (t + 2 < cnt) cp_tile(bB, gC + (size_t)jtN2 * TILE_GM, tid);
        if (t + 1 < cnt && itN != itC) {
            cp_tile(sb + SM_A, gC + (size_t)itN * TILE_GM, tid);
            nextAFresh = true;
        }
        CP_COMMIT();

        aFresh = nextAFresh;
        itC = itN; jtC = jtN;
        itN = itN2; jtN = jtN2;
        stepPair(itN2, jtN2);
    }
}

// ================= kernel 3: finalize (re-zeroes accumulators) =================
__global__ void __launch_bounds__(256) finalize_kernel(float* __restrict__ out) {
    const int tid = threadIdx.x;
    __shared__ float buf[8];

    float lsum = 0.f;
    for (int i = tid; i < TBROWS; i += 256) {
        lsum += logf(g_rowE[i]);
        g_rowE[i] = 0.f;
    }
    float v = g_colV[tid];
    g_colV[tid] = 0.f;
    float s2 = v * v;
    float psum = g_posPart[tid] + g_posPart[tid + 256];

    float vals[3] = {lsum, s2, psum};
    float tot[3];
    #pragma unroll
    for (int vv = 0; vv < 3; vv++) {
        float x = vals[vv];
        #pragma unroll
        for (int o = 16; o > 0; o >>= 1) x += __shfl_xor_sync(~0u, x, o);
        if ((tid & 31) == 0) buf[tid >> 5] = x;
        __syncthreads();
        float r = 0.f;
        if (tid == 0) {
            #pragma unroll
            for (int i = 0; i < 8; i++) r += buf[i];
        }
        __syncthreads();
        tot[vv] = r;
    }
    if (tid == 0) {
        double logSum = tot[0];
        double sSum   = (double)tot[1] - (double)TBROWS;   // sum_offdiag s
        double posSum = tot[2];
        double negMean = (10.0 * sSum - (double)(TBROWS - 1) * logSum)
                       / (4.0 * (double)BROWS * (double)BROWS);
        out[0] = (float)(-(posSum / (double)BROWS) * 10.0 + negMean);
    }
}

// ================= launch =================
extern "C" void kernel_launch(void* const* d_in, const int* in_sizes, int n_in,
                              void* d_out, int out_size) {
    const float* x1 = (const float*)d_in[0];
    const float* x2 = (const float*)d_in[1];
    float* out = (float*)d_out;

    normalize_kernel<<<512, 256>>>(x1, x2);
    cudaFuncSetAttribute(sim_kernel, cudaFuncAttributeMaxDynamicSharedMemorySize, SM_TOTAL);
    sim_kernel<<<GRID_S, 256, SM_TOTAL>>>();
    finalize_kernel<<<1, 256>>>(out);
}

// round 10
// speedup vs baseline: 3.4852x; 3.4852x over previous
#include <cuda_runtime.h>
#include <cuda_bf16.h>
#include <cstdint>

// ContrastiveLoss B=4096, F=256.
// loss = -mean(pos)/T + [10*sum_offdiag(s) - (2B-1)*sum_i LSE_i]/(4B^2)
// INT8 mma.sync m16n8k32 (q=round(127c), s=i/16129), upper-triangle tiles only,
// sum_offdiag(s) = ||sum_i c_i||^2 - 2B (analytic).
// R10: colV via per-block partials (NO global atomics; R9's 256-hot-address REDG was 162us).

#define BROWS  4096
#define FDIM   256
#define TBROWS 8192
#define TM     128
#define NTILES 64
#define GRID_S 296
#define GROWB  256
#define SSTR   272
#define TILE_SM (TM * SSTR)            // 34816
#define TILE_GM (TM * GROWB)           // 32768

// ---------------- scratch (zero-init at load; finalize re-zeroes rowE) ----------------
__device__ __align__(16) int8_t g_Cq[TBROWS * FDIM];
__device__ float g_rowE[TBROWS];
__device__ float g_colPart[512 * FDIM];    // per-block feature-sum partials (plain stores)
__device__ float g_posPart[512];

__device__ __forceinline__ float ex2_mufu(float x) {
    float r;
    asm("ex2.approx.f32 %0, %1;" : "=f"(r) : "f"(x));
    return r;
}

// ================= kernel 1: normalize + quantize + pos sim + colsum partials =================
__global__ void __launch_bounds__(256) normalize_kernel(
    const float* __restrict__ x1, const float* __restrict__ x2)
{
    int warp = threadIdx.x >> 5, lane = threadIdx.x & 31;
    int r = blockIdx.x * 8 + warp;
    const float4* a4 = reinterpret_cast<const float4*>(x1 + (size_t)r * FDIM);
    const float4* b4 = reinterpret_cast<const float4*>(x2 + (size_t)r * FDIM);
    float4 a0 = a4[lane], a1 = a4[lane + 32];     // features 4l..4l+3, 128+4l..+3
    float4 b0 = b4[lane], b1 = b4[lane + 32];

    float ss1 = a0.x*a0.x+a0.y*a0.y+a0.z*a0.z+a0.w*a0.w + a1.x*a1.x+a1.y*a1.y+a1.z*a1.z+a1.w*a1.w;
    float ss2 = b0.x*b0.x+b0.y*b0.y+b0.z*b0.z+b0.w*b0.w + b1.x*b1.x+b1.y*b1.y+b1.z*b1.z+b1.w*b1.w;
    float dt  = a0.x*b0.x+a0.y*b0.y+a0.z*b0.z+a0.w*b0.w + a1.x*b1.x+a1.y*b1.y+a1.z*b1.z+a1.w*b1.w;
    #pragma unroll
    for (int o = 16; o > 0; o >>= 1) {
        ss1 += __shfl_xor_sync(~0u, ss1, o);
        ss2 += __shfl_xor_sync(~0u, ss2, o);
        dt  += __shfl_xor_sync(~0u, dt,  o);
    }
    float inv1 = 1.0f / fmaxf(sqrtf(ss1), 1e-7f);
    float inv2 = 1.0f / fmaxf(sqrtf(ss2), 1e-7f);

    float av[8] = {a0.x,a0.y,a0.z,a0.w,a1.x,a1.y,a1.z,a1.w};
    float bv[8] = {b0.x,b0.y,b0.z,b0.w,b1.x,b1.y,b1.z,b1.w};
    int8_t qa[8], qb[8];
    #pragma unroll
    for (int j = 0; j < 8; j++) {
        qa[j] = (int8_t)__float2int_rn(127.f * av[j] * inv1);
        qb[j] = (int8_t)__float2int_rn(127.f * bv[j] * inv2);
    }
    char* o1 = reinterpret_cast<char*>(g_Cq) + (size_t)r * FDIM;
    char* o2 = reinterpret_cast<char*>(g_Cq) + (size_t)(r + BROWS) * FDIM;
    *reinterpret_cast<uint32_t*>(o1 + 4*lane)       = *reinterpret_cast<uint32_t*>(qa);
    *reinterpret_cast<uint32_t*>(o1 + 128 + 4*lane) = *reinterpret_cast<uint32_t*>(qa + 4);
    *reinterpret_cast<uint32_t*>(o2 + 4*lane)       = *reinterpret_cast<uint32_t*>(qb);
    *reinterpret_cast<uint32_t*>(o2 + 128 + 4*lane) = *reinterpret_cast<uint32_t*>(qb + 4);

    // column sums: per-warp smem slices -> per-block partial store (no atomics anywhere)
    __shared__ float wsm[8 * FDIM];
    __shared__ float ps[8];
    float* ws = wsm + warp * FDIM;
    #pragma unroll
    for (int j = 0; j < 4; j++) {
        ws[4*lane + j]       = av[j]   * inv1 + bv[j]   * inv2;
        ws[128 + 4*lane + j] = av[4+j] * inv1 + bv[4+j] * inv2;
    }
    if (lane == 0) ps[warp] = dt * inv1 * inv2;
    __syncthreads();
    {
        int f = threadIdx.x;                      // 256 threads == 256 features
        float v = 0.f;
        #pragma unroll
        for (int w = 0; w < 8; w++) v += wsm[w * FDIM + f];
        g_colPart[(size_t)blockIdx.x * FDIM + f] = v;
    }
    if (threadIdx.x == 0) {
        float s = 0.f;
        #pragma unroll
        for (int i = 0; i < 8; i++) s += ps[i];
        g_posPart[blockIdx.x] = s;
    }
}

// ================= helpers =================
__device__ __forceinline__ uint32_t smem_u32(const void* p) {
    uint32_t a;
    asm("{ .reg .u64 t; cvta.to.shared.u64 t, %1; cvt.u32.u64 %0, t; }" : "=r"(a) : "l"(p));
    return a;
}
#define CP16(dst, src) \
    asm volatile("cp.async.cg.shared.global [%0], [%1], 16;" :: "r"(dst), "l"(src) : "memory")
#define CP_COMMIT() asm volatile("cp.async.commit_group;" ::: "memory")
#define CP_WAIT0()  asm volatile("cp.async.wait_group 0;" ::: "memory")
#define CP_WAIT1()  asm volatile("cp.async.wait_group 1;" ::: "memory")

#define LDM4(R, ADDR) \
    asm volatile("ldmatrix.sync.aligned.m8n8.x4.shared.b16 {%0,%1,%2,%3}, [%4];" \
        : "=r"((R)[0]), "=r"((R)[1]), "=r"((R)[2]), "=r"((R)[3]) : "r"(ADDR))

#define MMAI8(ACC, RA, B0, B1) \
    asm volatile("mma.sync.aligned.m16n8k32.row.col.s32.s8.s8.s32 " \
        "{%0,%1,%2,%3},{%4,%5,%6,%7},{%8,%9},{%0,%1,%2,%3};" \
        : "+r"((ACC)[0]), "+r"((ACC)[1]), "+r"((ACC)[2]), "+r"((ACC)[3]) \
        : "r"((RA)[0]), "r"((RA)[1]), "r"((RA)[2]), "r"((RA)[3]), "r"(B0), "r"(B1))

__device__ __forceinline__ void cp_tile(uint32_t dstBase, const char* src, int tid) {
    #pragma unroll
    for (int i = 0; i < 8; i++) {
        int idx = tid + i * 256;
        int row = idx >> 4, c = idx & 15;
        CP16(dstBase + row * SSTR + c * 16, src + row * GROWB + c * 16);
    }
}
__device__ __forceinline__ void stepPair(int& it, int& jt) {
    if (++jt == NTILES) { ++it; jt = it; }
}

#define SM_A  0
#define SM_B0 TILE_SM
#define SM_B1 (2 * TILE_SM)
#define SM_TOTAL (3 * TILE_SM)    // 104448 -> 2 CTAs/SM

// ================= kernel 2: int8 triangle GEMM + MUFU exp epilogue =================
__global__ void __launch_bounds__(256, 2) sim_kernel() {
    extern __shared__ char smem[];
    const uint32_t sb = smem_u32(smem);
    const int tid = threadIdx.x, warp = tid >> 5, lane = tid & 31;
    const int wm = warp >> 2, wn = warp & 3;
    const int grp = lane >> 2, qid = lane & 3;
    const int b = blockIdx.x;

    const int cnt = 7 + (b < 8);                  // 296*7 + 8 = 2080
    const int p0  = b * 7 + (b < 8 ? b : 8);
    int itC = 0, cum = 0;
    while (cum + (NTILES - itC) <= p0) { cum += NTILES - itC; ++itC; }
    int jtC = itC + (p0 - cum);
    int itN = itC, jtN = jtC;   stepPair(itN, jtN);
    int itN2 = itN, jtN2 = jtN; stepPair(itN2, jtN2);

    const char* gC = reinterpret_cast<const char*>(g_Cq);

    cp_tile(sb + SM_A,  gC + (size_t)itC * TILE_GM, tid);
    cp_tile(sb + SM_B0, gC + (size_t)jtC * TILE_GM, tid);
    CP_COMMIT();
    cp_tile(sb + SM_B1, gC + (size_t)jtN * TILE_GM, tid);
    CP_COMMIT();

    const uint32_t lrow = lane & 15, lhi = (lane >> 4) * 16;
    uint32_t aOff[4], bOff[2];
    #pragma unroll
    for (int mf = 0; mf < 4; mf++) aOff[mf] = sb + SM_A + (wm * 64 + mf * 16 + lrow) * SSTR + lhi;
    #pragma unroll
    for (int h = 0; h < 2; h++)    bOff[h] = (wn * 32 + h * 16 + lrow) * SSTR + lhi;

    bool aFresh = false;
    const float SC = 14.426950408889634f / 16129.0f;   // exp(10*i/127^2) = 2^(i*SC)

    for (int t = 0; t < cnt; t++) {
        if (aFresh) CP_WAIT0(); else CP_WAIT1();
        __syncthreads();
        const uint32_t bB = sb + ((t & 1) ? SM_B1 : SM_B0);

        int acc[4][4][4];
        #pragma unroll
        for (int mf = 0; mf < 4; mf++)
            #pragma unroll
            for (int nf = 0; nf < 4; nf++)
                #pragma unroll
                for (int k = 0; k < 4; k++) acc[mf][nf][k] = 0;

        #pragma unroll
        for (int kk = 0; kk < 8; kk++) {
            uint32_t ra[4][4], rb[2][4];
            #pragma unroll
            for (int mf = 0; mf < 4; mf++) LDM4(ra[mf], aOff[mf] + kk * 32);
            #pragma unroll
            for (int h = 0; h < 2; h++)    LDM4(rb[h], bB + bOff[h] + kk * 32);
            #pragma unroll
            for (int mf = 0; mf < 4; mf++) {
                #pragma unroll
                for (int h = 0; h < 2; h++) {
                    MMAI8(acc[mf][2*h+0], ra[mf], rb[h][0], rb[h][2]);
                    MMAI8(acc[mf][2*h+1], ra[mf], rb[h][1], rb[h][3]);
                }
            }
        }

        // ---- epilogue BEFORE barrier (overlaps other warps' MMA) ----
        const bool dg = (itC == jtC);
        float rs[8];
        #pragma unroll
        for (int i = 0; i < 8; i++) rs[i] = 0.f;

        if (!dg) {
            float cs[8];
            #pragma unroll
            for (int i = 0; i < 8; i++) cs[i] = 0.f;
            #pragma unroll
            for (int mf = 0; mf < 4; mf++)
                #pragma unroll
                for (int nf = 0; nf < 4; nf++)
                    #pragma unroll
                    for (int k = 0; k < 4; k++) {
                        float e = ex2_mufu((float)acc[mf][nf][k] * SC);
                        rs[mf*2 + (k >> 1)] += e;
                        cs[nf*2 + (k & 1)] += e;
                    }
            #pragma unroll
            for (int i = 0; i < 8; i++) {
                rs[i] += __shfl_xor_sync(~0u, rs[i], 1);
                rs[i] += __shfl_xor_sync(~0u, rs[i], 2);
                cs[i] += __shfl_xor_sync(~0u, cs[i], 4);
                cs[i] += __shfl_xor_sync(~0u, cs[i], 8);
                cs[i] += __shfl_xor_sync(~0u, cs[i], 16);
            }
            if (qid == 0) {
                #pragma unroll
                for (int mf = 0; mf < 4; mf++)
                    #pragma unroll
                    for (int h = 0; h < 2; h++)
                        atomicAdd(&g_rowE[itC*TM + wm*64 + mf*16 + h*8 + grp], rs[mf*2 + h]);
            }
            if (grp == 0) {
                #pragma unroll
                for (int nf = 0; nf < 4; nf++)
                    #pragma unroll
                    for (int par = 0; par < 2; par++)
                        atomicAdd(&g_rowE[jtC*TM + wn*32 + nf*8 + 2*qid + par], cs[nf*2 + par]);
            }
        } else {
            #pragma unroll
            for (int mf = 0; mf < 4; mf++)
                #pragma unroll
                for (int nf = 0; nf < 4; nf++)
                    #pragma unroll
                    for (int k = 0; k < 4; k++) {
                        int rl = wm*64 + mf*16 + grp + (k >> 1)*8;
                        int cl = wn*32 + nf*8 + 2*qid + (k & 1);
                        if (rl != cl) {
                            float e = ex2_mufu((float)acc[mf][nf][k] * SC);
                            rs[mf*2 + (k >> 1)] += e;
                        }
                    }
            #pragma unroll
            for (int i = 0; i < 8; i++) {
                rs[i] += __shfl_xor_sync(~0u, rs[i], 1);
                rs[i] += __shfl_xor_sync(~0u, rs[i], 2);
            }
            if (qid == 0) {
                #pragma unroll
                for (int mf = 0; mf < 4; mf++)
                    #pragma unroll
                    for (int h = 0; h < 2; h++)
                        atomicAdd(&g_rowE[itC*TM + wm*64 + mf*16 + h*8 + grp], rs[mf*2 + h]);
            }
        }

        __syncthreads();                           // all warps done reading smem tiles
        bool nextAFresh = false;
        if (t + 2 < cnt) cp_tile(bB, gC + (size_t)jtN2 * TILE_GM, tid);
        if (t + 1 < cnt && itN != itC) {
            cp_tile(sb + SM_A, gC + (size_t)itN * TILE_GM, tid);
            nextAFresh = true;
        }
        CP_COMMIT();

        aFresh = nextAFresh;
        itC = itN; jtC = jtN;
        itN = itN2; jtN = jtN2;
        stepPair(itN2, jtN2);
    }
}

// ================= kernel 3: finalize (re-zeroes rowE for next replay) =================
__global__ void __launch_bounds__(256) finalize_kernel(float* __restrict__ out) {
    const int tid = threadIdx.x;
    __shared__ float buf[8];

    float lsum = 0.f;
    for (int i = tid; i < TBROWS; i += 256) {
        lsum += logf(g_rowE[i]);
        g_rowE[i] = 0.f;
    }
    float v = 0.f;                                 // column sum for feature tid
    for (int bb = 0; bb < 512; bb++)
        v += g_colPart[(size_t)bb * FDIM + tid];
    float s2 = v * v;
    float psum = g_posPart[tid] + g_posPart[tid + 256];

    float vals[3] = {lsum, s2, psum};
    float tot[3];
    #pragma unroll
    for (int vv = 0; vv < 3; vv++) {
        float x = vals[vv];
        #pragma unroll
        for (int o = 16; o > 0; o >>= 1) x += __shfl_xor_sync(~0u, x, o);
        if ((tid & 31) == 0) buf[tid >> 5] = x;
        __syncthreads();
        float r = 0.f;
        if (tid == 0) {
            #pragma unroll
            for (int i = 0; i < 8; i++) r += buf[i];
        }
        __syncthreads();
        tot[vv] = r;
    }
    if (tid == 0) {
        double logSum = tot[0];
        double sSum   = (double)tot[1] - (double)TBROWS;   // sum_offdiag s
        double posSum = tot[2];
        double negMean = (10.0 * sSum - (double)(TBROWS - 1) * logSum)
                       / (4.0 * (double)BROWS * (double)BROWS);
        out[0] = (float)(-(posSum / (double)BROWS) * 10.0 + negMean);
    }
}

// ================= launch =================
extern "C" void kernel_launch(void* const* d_in, const int* in_sizes, int n_in,
                              void* d_out, int out_size) {
    const float* x1 = (const float*)d_in[0];
    const float* x2 = (const float*)d_in[1];
    float* out = (float*)d_out;

    normalize_kernel<<<512, 256>>>(x1, x2);
    cudaFuncSetAttribute(sim_kernel, cudaFuncAttributeMaxDynamicSharedMemorySize, SM_TOTAL);
    sim_kernel<<<GRID_S, 256, SM_TOTAL>>>();
    finalize_kernel<<<1, 256>>>(out);
}

// round 11
// speedup vs baseline: 3.8848x; 1.1146x over previous
#include <cuda_runtime.h>
#include <cuda_bf16.h>
#include <cstdint>

// ContrastiveLoss B=4096, F=256.
// loss = -mean(pos)/T + [10*sum_offdiag(s) - (2B-1)*sum_i LSE_i]/(4B^2)
// INT8 mma.sync m16n8k32 (q=round(127c), s=i/16129), upper-triangle tiles only,
// sum_offdiag(s) = ||sum_i c_i||^2 - 2B (analytic).
// R11: finalize parallelized to 1024 threads (R10's 1-block colPart sum was ~10.5us latency-bound).

#define BROWS  4096
#define FDIM   256
#define TBROWS 8192
#define TM     128
#define NTILES 64
#define GRID_S 296
#define GROWB  256
#define SSTR   272
#define TILE_SM (TM * SSTR)            // 34816
#define TILE_GM (TM * GROWB)           // 32768

// ---------------- scratch (zero-init at load; finalize re-zeroes rowE) ----------------
__device__ __align__(16) int8_t g_Cq[TBROWS * FDIM];
__device__ float g_rowE[TBROWS];
__device__ float g_colPart[512 * FDIM];    // per-block feature-sum partials (plain stores)
__device__ float g_posPart[512];

__device__ __forceinline__ float ex2_mufu(float x) {
    float r;
    asm("ex2.approx.f32 %0, %1;" : "=f"(r) : "f"(x));
    return r;
}

// ================= kernel 1: normalize + quantize + pos sim + colsum partials =================
__global__ void __launch_bounds__(256) normalize_kernel(
    const float* __restrict__ x1, const float* __restrict__ x2)
{
    int warp = threadIdx.x >> 5, lane = threadIdx.x & 31;
    int r = blockIdx.x * 8 + warp;
    const float4* a4 = reinterpret_cast<const float4*>(x1 + (size_t)r * FDIM);
    const float4* b4 = reinterpret_cast<const float4*>(x2 + (size_t)r * FDIM);
    float4 a0 = a4[lane], a1 = a4[lane + 32];     // features 4l..4l+3, 128+4l..+3
    float4 b0 = b4[lane], b1 = b4[lane + 32];

    float ss1 = a0.x*a0.x+a0.y*a0.y+a0.z*a0.z+a0.w*a0.w + a1.x*a1.x+a1.y*a1.y+a1.z*a1.z+a1.w*a1.w;
    float ss2 = b0.x*b0.x+b0.y*b0.y+b0.z*b0.z+b0.w*b0.w + b1.x*b1.x+b1.y*b1.y+b1.z*b1.z+b1.w*b1.w;
    float dt  = a0.x*b0.x+a0.y*b0.y+a0.z*b0.z+a0.w*b0.w + a1.x*b1.x+a1.y*b1.y+a1.z*b1.z+a1.w*b1.w;
    #pragma unroll
    for (int o = 16; o > 0; o >>= 1) {
        ss1 += __shfl_xor_sync(~0u, ss1, o);
        ss2 += __shfl_xor_sync(~0u, ss2, o);
        dt  += __shfl_xor_sync(~0u, dt,  o);
    }
    float inv1 = 1.0f / fmaxf(sqrtf(ss1), 1e-7f);
    float inv2 = 1.0f / fmaxf(sqrtf(ss2), 1e-7f);

    float av[8] = {a0.x,a0.y,a0.z,a0.w,a1.x,a1.y,a1.z,a1.w};
    float bv[8] = {b0.x,b0.y,b0.z,b0.w,b1.x,b1.y,b1.z,b1.w};
    int8_t qa[8], qb[8];
    #pragma unroll
    for (int j = 0; j < 8; j++) {
        qa[j] = (int8_t)__float2int_rn(127.f * av[j] * inv1);
        qb[j] = (int8_t)__float2int_rn(127.f * bv[j] * inv2);
    }
    char* o1 = reinterpret_cast<char*>(g_Cq) + (size_t)r * FDIM;
    char* o2 = reinterpret_cast<char*>(g_Cq) + (size_t)(r + BROWS) * FDIM;
    *reinterpret_cast<uint32_t*>(o1 + 4*lane)       = *reinterpret_cast<uint32_t*>(qa);
    *reinterpret_cast<uint32_t*>(o1 + 128 + 4*lane) = *reinterpret_cast<uint32_t*>(qa + 4);
    *reinterpret_cast<uint32_t*>(o2 + 4*lane)       = *reinterpret_cast<uint32_t*>(qb);
    *reinterpret_cast<uint32_t*>(o2 + 128 + 4*lane) = *reinterpret_cast<uint32_t*>(qb + 4);

    // column sums: per-warp smem slices -> per-block partial store (no atomics anywhere)
    __shared__ float wsm[8 * FDIM];
    __shared__ float ps[8];
    float* ws = wsm + warp * FDIM;
    #pragma unroll
    for (int j = 0; j < 4; j++) {
        ws[4*lane + j]       = av[j]   * inv1 + bv[j]   * inv2;
        ws[128 + 4*lane + j] = av[4+j] * inv1 + bv[4+j] * inv2;
    }
    if (lane == 0) ps[warp] = dt * inv1 * inv2;
    __syncthreads();
    {
        int f = threadIdx.x;                      // 256 threads == 256 features
        float v = 0.f;
        #pragma unroll
        for (int w = 0; w < 8; w++) v += wsm[w * FDIM + f];
        g_colPart[(size_t)blockIdx.x * FDIM + f] = v;
    }
    if (threadIdx.x == 0) {
        float s = 0.f;
        #pragma unroll
        for (int i = 0; i < 8; i++) s += ps[i];
        g_posPart[blockIdx.x] = s;
    }
}

// ================= helpers =================
__device__ __forceinline__ uint32_t smem_u32(const void* p) {
    uint32_t a;
    asm("{ .reg .u64 t; cvta.to.shared.u64 t, %1; cvt.u32.u64 %0, t; }" : "=r"(a) : "l"(p));
    return a;
}
#define CP16(dst, src) \
    asm volatile("cp.async.cg.shared.global [%0], [%1], 16;" :: "r"(dst), "l"(src) : "memory")
#define CP_COMMIT() asm volatile("cp.async.commit_group;" ::: "memory")
#define CP_WAIT0()  asm volatile("cp.async.wait_group 0;" ::: "memory")
#define CP_WAIT1()  asm volatile("cp.async.wait_group 1;" ::: "memory")

#define LDM4(R, ADDR) \
    asm volatile("ldmatrix.sync.aligned.m8n8.x4.shared.b16 {%0,%1,%2,%3}, [%4];" \
        : "=r"((R)[0]), "=r"((R)[1]), "=r"((R)[2]), "=r"((R)[3]) : "r"(ADDR))

#define MMAI8(ACC, RA, B0, B1) \
    asm volatile("mma.sync.aligned.m16n8k32.row.col.s32.s8.s8.s32 " \
        "{%0,%1,%2,%3},{%4,%5,%6,%7},{%8,%9},{%0,%1,%2,%3};" \
        : "+r"((ACC)[0]), "+r"((ACC)[1]), "+r"((ACC)[2]), "+r"((ACC)[3]) \
        : "r"((RA)[0]), "r"((RA)[1]), "r"((RA)[2]), "r"((RA)[3]), "r"(B0), "r"(B1))

__device__ __forceinline__ void cp_tile(uint32_t dstBase, const char* src, int tid) {
    #pragma unroll
    for (int i = 0; i < 8; i++) {
        int idx = tid + i * 256;
        int row = idx >> 4, c = idx & 15;
        CP16(dstBase + row * SSTR + c * 16, src + row * GROWB + c * 16);
    }
}
__device__ __forceinline__ void stepPair(int& it, int& jt) {
    if (++jt == NTILES) { ++it; jt = it; }
}

#define SM_A  0
#define SM_B0 TILE_SM
#define SM_B1 (2 * TILE_SM)
#define SM_TOTAL (3 * TILE_SM)    // 104448 -> 2 CTAs/SM

// ================= kernel 2: int8 triangle GEMM + MUFU exp epilogue =================
__global__ void __launch_bounds__(256, 2) sim_kernel() {
    extern __shared__ char smem[];
    const uint32_t sb = smem_u32(smem);
    const int tid = threadIdx.x, warp = tid >> 5, lane = tid & 31;
    const int wm = warp >> 2, wn = warp & 3;
    const int grp = lane >> 2, qid = lane & 3;
    const int b = blockIdx.x;

    const int cnt = 7 + (b < 8);                  // 296*7 + 8 = 2080
    const int p0  = b * 7 + (b < 8 ? b : 8);
    int itC = 0, cum = 0;
    while (cum + (NTILES - itC) <= p0) { cum += NTILES - itC; ++itC; }
    int jtC = itC + (p0 - cum);
    int itN = itC, jtN = jtC;   stepPair(itN, jtN);
    int itN2 = itN, jtN2 = jtN; stepPair(itN2, jtN2);

    const char* gC = reinterpret_cast<const char*>(g_Cq);

    cp_tile(sb + SM_A,  gC + (size_t)itC * TILE_GM, tid);
    cp_tile(sb + SM_B0, gC + (size_t)jtC * TILE_GM, tid);
    CP_COMMIT();
    cp_tile(sb + SM_B1, gC + (size_t)jtN * TILE_GM, tid);
    CP_COMMIT();

    const uint32_t lrow = lane & 15, lhi = (lane >> 4) * 16;
    uint32_t aOff[4], bOff[2];
    #pragma unroll
    for (int mf = 0; mf < 4; mf++) aOff[mf] = sb + SM_A + (wm * 64 + mf * 16 + lrow) * SSTR + lhi;
    #pragma unroll
    for (int h = 0; h < 2; h++)    bOff[h] = (wn * 32 + h * 16 + lrow) * SSTR + lhi;

    bool aFresh = false;
    const float SC = 14.426950408889634f / 16129.0f;   // exp(10*i/127^2) = 2^(i*SC)

    for (int t = 0; t < cnt; t++) {
        if (aFresh) CP_WAIT0(); else CP_WAIT1();
        __syncthreads();
        const uint32_t bB = sb + ((t & 1) ? SM_B1 : SM_B0);

        int acc[4][4][4];
        #pragma unroll
        for (int mf = 0; mf < 4; mf++)
            #pragma unroll
            for (int nf = 0; nf < 4; nf++)
                #pragma unroll
                for (int k = 0; k < 4; k++) acc[mf][nf][k] = 0;

        #pragma unroll
        for (int kk = 0; kk < 8; kk++) {
            uint32_t ra[4][4], rb[2][4];
            #pragma unroll
            for (int mf = 0; mf < 4; mf++) LDM4(ra[mf], aOff[mf] + kk * 32);
            #pragma unroll
            for (int h = 0; h < 2; h++)    LDM4(rb[h], bB + bOff[h] + kk * 32);
            #pragma unroll
            for (int mf = 0; mf < 4; mf++) {
                #pragma unroll
                for (int h = 0; h < 2; h++) {
                    MMAI8(acc[mf][2*h+0], ra[mf], rb[h][0], rb[h][2]);
                    MMAI8(acc[mf][2*h+1], ra[mf], rb[h][1], rb[h][3]);
                }
            }
        }

        // ---- epilogue BEFORE barrier (overlaps other warps' MMA) ----
        const bool dg = (itC == jtC);
        float rs[8];
        #pragma unroll
        for (int i = 0; i < 8; i++) rs[i] = 0.f;

        if (!dg) {
            float cs[8];
            #pragma unroll
            for (int i = 0; i < 8; i++) cs[i] = 0.f;
            #pragma unroll
            for (int mf = 0; mf < 4; mf++)
                #pragma unroll
                for (int nf = 0; nf < 4; nf++)
                    #pragma unroll
                    for (int k = 0; k < 4; k++) {
                        float e = ex2_mufu((float)acc[mf][nf][k] * SC);
                        rs[mf*2 + (k >> 1)] += e;
                        cs[nf*2 + (k & 1)] += e;
                    }
            #pragma unroll
            for (int i = 0; i < 8; i++) {
                rs[i] += __shfl_xor_sync(~0u, rs[i], 1);
                rs[i] += __shfl_xor_sync(~0u, rs[i], 2);
                cs[i] += __shfl_xor_sync(~0u, cs[i], 4);
                cs[i] += __shfl_xor_sync(~0u, cs[i], 8);
                cs[i] += __shfl_xor_sync(~0u, cs[i], 16);
            }
            if (qid == 0) {
                #pragma unroll
                for (int mf = 0; mf < 4; mf++)
                    #pragma unroll
                    for (int h = 0; h < 2; h++)
                        atomicAdd(&g_rowE[itC*TM + wm*64 + mf*16 + h*8 + grp], rs[mf*2 + h]);
            }
            if (grp == 0) {
                #pragma unroll
                for (int nf = 0; nf < 4; nf++)
                    #pragma unroll
                    for (int par = 0; par < 2; par++)
                        atomicAdd(&g_rowE[jtC*TM + wn*32 + nf*8 + 2*qid + par], cs[nf*2 + par]);
            }
        } else {
            #pragma unroll
            for (int mf = 0; mf < 4; mf++)
                #pragma unroll
                for (int nf = 0; nf < 4; nf++)
                    #pragma unroll
                    for (int k = 0; k < 4; k++) {
                        int rl = wm*64 + mf*16 + grp + (k >> 1)*8;
                        int cl = wn*32 + nf*8 + 2*qid + (k & 1);
                        if (rl != cl) {
                            float e = ex2_mufu((float)acc[mf][nf][k] * SC);
                            rs[mf*2 + (k >> 1)] += e;
                        }
                    }
            #pragma unroll
            for (int i = 0; i < 8; i++) {
                rs[i] += __shfl_xor_sync(~0u, rs[i], 1);
                rs[i] += __shfl_xor_sync(~0u, rs[i], 2);
            }
            if (qid == 0) {
                #pragma unroll
                for (int mf = 0; mf < 4; mf++)
                    #pragma unroll
                    for (int h = 0; h < 2; h++)
                        atomicAdd(&g_rowE[itC*TM + wm*64 + mf*16 + h*8 + grp], rs[mf*2 + h]);
            }
        }

        __syncthreads();                           // all warps done reading smem tiles
        bool nextAFresh = false;
        if (t + 2 < cnt) cp_tile(bB, gC + (size_t)jtN2 * TILE_GM, tid);
        if (t + 1 < cnt && itN != itC) {
            cp_tile(sb + SM_A, gC + (size_t)itN * TILE_GM, tid);
            nextAFresh = true;
        }
        CP_COMMIT();

        aFresh = nextAFresh;
        itC = itN; jtC = jtN;
        itN = itN2; jtN = jtN2;
        stepPair(itN2, jtN2);
    }
}

// ================= kernel 3: finalize, 1024 threads (re-zeroes rowE) =================
__global__ void __launch_bounds__(1024) finalize_kernel(float* __restrict__ out) {
    const int tid = threadIdx.x;
    __shared__ float cbuf[1024];
    __shared__ float buf[32];

    // rowE logs: 8 per thread
    float lsum = 0.f;
    #pragma unroll
    for (int i = tid; i < TBROWS; i += 1024) {
        lsum += logf(g_rowE[i]);
        g_rowE[i] = 0.f;
    }

    // colPart: 4 groups of 256 threads each sum 128 block-partials (coalesced)
    const int f = tid & 255, g4 = tid >> 8;
    float v = 0.f;
    #pragma unroll 8
    for (int bb = g4 * 128; bb < g4 * 128 + 128; bb++)
        v += g_colPart[(size_t)bb * FDIM + f];
    cbuf[tid] = v;
    __syncthreads();
    float s2 = 0.f;
    if (tid < 256) {
        float vf = cbuf[tid] + cbuf[tid + 256] + cbuf[tid + 512] + cbuf[tid + 768];
        s2 = vf * vf;
    }
    float psum = (tid < 512) ? g_posPart[tid] : 0.f;

    // deterministic reductions over 32 warps
    float vals[3] = {lsum, s2, psum};
    float tot[3];
    #pragma unroll
    for (int vv = 0; vv < 3; vv++) {
        float x = vals[vv];
        #pragma unroll
        for (int o = 16; o > 0; o >>= 1) x += __shfl_xor_sync(~0u, x, o);
        __syncthreads();
        if ((tid & 31) == 0) buf[tid >> 5] = x;
        __syncthreads();
        float r = 0.f;
        if (tid == 0) {
            #pragma unroll
            for (int i = 0; i < 32; i++) r += buf[i];
        }
        tot[vv] = r;
    }
    if (tid == 0) {
        double logSum = tot[0];
        double sSum   = (double)tot[1] - (double)TBROWS;   // sum_offdiag s
        double posSum = tot[2];
        double negMean = (10.0 * sSum - (double)(TBROWS - 1) * logSum)
                       / (4.0 * (double)BROWS * (double)BROWS);
        out[0] = (float)(-(posSum / (double)BROWS) * 10.0 + negMean);
    }
}

// ================= launch =================
extern "C" void kernel_launch(void* const* d_in, const int* in_sizes, int n_in,
                              void* d_out, int out_size) {
    const float* x1 = (const float*)d_in[0];
    const float* x2 = (const float*)d_in[1];
    float* out = (float*)d_out;

    normalize_kernel<<<512, 256>>>(x1, x2);
    cudaFuncSetAttribute(sim_kernel, cudaFuncAttributeMaxDynamicSharedMemorySize, SM_TOTAL);
    sim_kernel<<<GRID_S, 256, SM_TOTAL>>>();
    finalize_kernel<<<1, 1024>>>(out);
}

// round 12
// speedup vs baseline: 3.9224x; 1.0097x over previous
#include <cuda_runtime.h>
#include <cuda_bf16.h>
#include <cstdint>

// ContrastiveLoss B=4096, F=256.
// loss = -mean(pos)/T + [10*sum_offdiag(s) - (2B-1)*sum_i LSE_i]/(4B^2)
// INT8 mma.sync m16n8k32 (q=round(127c), s=i/16129), upper-triangle tiles only,
// sum_offdiag(s) = ||sum_i c_i||^2 - 2B (analytic).
// R12: pre-biased accumulators (init 0x4B400000) -> epilogue = FFMA + MUFU.EX2 only
// (no I2F, no FMUL). Tests whether CVT was the hidden xu-pipe load.

#define BROWS  4096
#define FDIM   256
#define TBROWS 8192
#define TM     128
#define NTILES 64
#define GRID_S 296
#define GROWB  256
#define SSTR   272
#define TILE_SM (TM * SSTR)            // 34816
#define TILE_GM (TM * GROWB)           // 32768
#define ACCBIAS 0x4B400000             // float 12582912.0 bit pattern; |dot| < 2^22 guaranteed

// ---------------- scratch (zero-init at load; finalize re-zeroes rowE) ----------------
__device__ __align__(16) int8_t g_Cq[TBROWS * FDIM];
__device__ float g_rowE[TBROWS];
__device__ float g_colPart[512 * FDIM];    // per-block feature-sum partials (plain stores)
__device__ float g_posPart[512];

__device__ __forceinline__ float ex2_mufu(float x) {
    float r;
    asm("ex2.approx.f32 %0, %1;" : "=f"(r) : "f"(x));
    return r;
}

// ================= kernel 1: normalize + quantize + pos sim + colsum partials =================
__global__ void __launch_bounds__(256) normalize_kernel(
    const float* __restrict__ x1, const float* __restrict__ x2)
{
    int warp = threadIdx.x >> 5, lane = threadIdx.x & 31;
    int r = blockIdx.x * 8 + warp;
    const float4* a4 = reinterpret_cast<const float4*>(x1 + (size_t)r * FDIM);
    const float4* b4 = reinterpret_cast<const float4*>(x2 + (size_t)r * FDIM);
    float4 a0 = a4[lane], a1 = a4[lane + 32];     // features 4l..4l+3, 128+4l..+3
    float4 b0 = b4[lane], b1 = b4[lane + 32];

    float ss1 = a0.x*a0.x+a0.y*a0.y+a0.z*a0.z+a0.w*a0.w + a1.x*a1.x+a1.y*a1.y+a1.z*a1.z+a1.w*a1.w;
    float ss2 = b0.x*b0.x+b0.y*b0.y+b0.z*b0.z+b0.w*b0.w + b1.x*b1.x+b1.y*b1.y+b1.z*b1.z+b1.w*b1.w;
    float dt  = a0.x*b0.x+a0.y*b0.y+a0.z*b0.z+a0.w*b0.w + a1.x*b1.x+a1.y*b1.y+a1.z*b1.z+a1.w*b1.w;
    #pragma unroll
    for (int o = 16; o > 0; o >>= 1) {
        ss1 += __shfl_xor_sync(~0u, ss1, o);
        ss2 += __shfl_xor_sync(~0u, ss2, o);
        dt  += __shfl_xor_sync(~0u, dt,  o);
    }
    float inv1 = 1.0f / fmaxf(sqrtf(ss1), 1e-7f);
    float inv2 = 1.0f / fmaxf(sqrtf(ss2), 1e-7f);

    float av[8] = {a0.x,a0.y,a0.z,a0.w,a1.x,a1.y,a1.z,a1.w};
    float bv[8] = {b0.x,b0.y,b0.z,b0.w,b1.x,b1.y,b1.z,b1.w};
    int8_t qa[8], qb[8];
    #pragma unroll
    for (int j = 0; j < 8; j++) {
        qa[j] = (int8_t)__float2int_rn(127.f * av[j] * inv1);
        qb[j] = (int8_t)__float2int_rn(127.f * bv[j] * inv2);
    }
    char* o1 = reinterpret_cast<char*>(g_Cq) + (size_t)r * FDIM;
    char* o2 = reinterpret_cast<char*>(g_Cq) + (size_t)(r + BROWS) * FDIM;
    *reinterpret_cast<uint32_t*>(o1 + 4*lane)       = *reinterpret_cast<uint32_t*>(qa);
    *reinterpret_cast<uint32_t*>(o1 + 128 + 4*lane) = *reinterpret_cast<uint32_t*>(qa + 4);
    *reinterpret_cast<uint32_t*>(o2 + 4*lane)       = *reinterpret_cast<uint32_t*>(qb);
    *reinterpret_cast<uint32_t*>(o2 + 128 + 4*lane) = *reinterpret_cast<uint32_t*>(qb + 4);

    // column sums: per-warp smem slices -> per-block partial store (no atomics)
    __shared__ float wsm[8 * FDIM];
    __shared__ float ps[8];
    float* ws = wsm + warp * FDIM;
    #pragma unroll
    for (int j = 0; j < 4; j++) {
        ws[4*lane + j]       = av[j]   * inv1 + bv[j]   * inv2;
        ws[128 + 4*lane + j] = av[4+j] * inv1 + bv[4+j] * inv2;
    }
    if (lane == 0) ps[warp] = dt * inv1 * inv2;
    __syncthreads();
    {
        int f = threadIdx.x;                      // 256 threads == 256 features
        float v = 0.f;
        #pragma unroll
        for (int w = 0; w < 8; w++) v += wsm[w * FDIM + f];
        g_colPart[(size_t)blockIdx.x * FDIM + f] = v;
    }
    if (threadIdx.x == 0) {
        float s = 0.f;
        #pragma unroll
        for (int i = 0; i < 8; i++) s += ps[i];
        g_posPart[blockIdx.x] = s;
    }
}

// ================= helpers =================
__device__ __forceinline__ uint32_t smem_u32(const void* p) {
    uint32_t a;
    asm("{ .reg .u64 t; cvta.to.shared.u64 t, %1; cvt.u32.u64 %0, t; }" : "=r"(a) : "l"(p));
    return a;
}
#define CP16(dst, src) \
    asm volatile("cp.async.cg.shared.global [%0], [%1], 16;" :: "r"(dst), "l"(src) : "memory")
#define CP_COMMIT() asm volatile("cp.async.commit_group;" ::: "memory")
#define CP_WAIT0()  asm volatile("cp.async.wait_group 0;" ::: "memory")
#define CP_WAIT1()  asm volatile("cp.async.wait_group 1;" ::: "memory")

#define LDM4(R, ADDR) \
    asm volatile("ldmatrix.sync.aligned.m8n8.x4.shared.b16 {%0,%1,%2,%3}, [%4];" \
        : "=r"((R)[0]), "=r"((R)[1]), "=r"((R)[2]), "=r"((R)[3]) : "r"(ADDR))

#define MMAI8(ACC, RA, B0, B1) \
    asm volatile("mma.sync.aligned.m16n8k32.row.col.s32.s8.s8.s32 " \
        "{%0,%1,%2,%3},{%4,%5,%6,%7},{%8,%9},{%0,%1,%2,%3};" \
        : "+r"((ACC)[0]), "+r"((ACC)[1]), "+r"((ACC)[2]), "+r"((ACC)[3]) \
        : "r"((RA)[0]), "r"((RA)[1]), "r"((RA)[2]), "r"((RA)[3]), "r"(B0), "r"(B1))

__device__ __forceinline__ void cp_tile(uint32_t dstBase, const char* src, int tid) {
    #pragma unroll
    for (int i = 0; i < 8; i++) {
        int idx = tid + i * 256;
        int row = idx >> 4, c = idx & 15;
        CP16(dstBase + row * SSTR + c * 16, src + row * GROWB + c * 16);
    }
}
__device__ __forceinline__ void stepPair(int& it, int& jt) {
    if (++jt == NTILES) { ++it; jt = it; }
}

#define SM_A  0
#define SM_B0 TILE_SM
#define SM_B1 (2 * TILE_SM)
#define SM_TOTAL (3 * TILE_SM)    // 104448 -> 2 CTAs/SM

// ================= kernel 2: int8 triangle GEMM + biased-acc MUFU epilogue =================
__global__ void __launch_bounds__(256, 2) sim_kernel() {
    extern __shared__ char smem[];
    const uint32_t sb = smem_u32(smem);
    const int tid = threadIdx.x, warp = tid >> 5, lane = tid & 31;
    const int wm = warp >> 2, wn = warp & 3;
    const int grp = lane >> 2, qid = lane & 3;
    const int b = blockIdx.x;

    const int cnt = 7 + (b < 8);                  // 296*7 + 8 = 2080
    const int p0  = b * 7 + (b < 8 ? b : 8);
    int itC = 0, cum = 0;
    while (cum + (NTILES - itC) <= p0) { cum += NTILES - itC; ++itC; }
    int jtC = itC + (p0 - cum);
    int itN = itC, jtN = jtC;   stepPair(itN, jtN);
    int itN2 = itN, jtN2 = jtN; stepPair(itN2, jtN2);

    const char* gC = reinterpret_cast<const char*>(g_Cq);

    cp_tile(sb + SM_A,  gC + (size_t)itC * TILE_GM, tid);
    cp_tile(sb + SM_B0, gC + (size_t)jtC * TILE_GM, tid);
    CP_COMMIT();
    cp_tile(sb + SM_B1, gC + (size_t)jtN * TILE_GM, tid);
    CP_COMMIT();

    const uint32_t lrow = lane & 15, lhi = (lane >> 4) * 16;
    uint32_t aOff[4], bOff[2];
    #pragma unroll
    for (int mf = 0; mf < 4; mf++) aOff[mf] = sb + SM_A + (wm * 64 + mf * 16 + lrow) * SSTR + lhi;
    #pragma unroll
    for (int h = 0; h < 2; h++)    bOff[h] = (wn * 32 + h * 16 + lrow) * SSTR + lhi;

    bool aFresh = false;
    // exp(10*dot/16129) = 2^(dot*SC); acc = 12582912 + dot as float bits
    const float SCf = (float)(14.42695040888963407 / 16129.0);
    const float OFF = (float)(-12582912.0 * (double)((float)(14.42695040888963407 / 16129.0)));

    for (int t = 0; t < cnt; t++) {
        if (aFresh) CP_WAIT0(); else CP_WAIT1();
        __syncthreads();
        const uint32_t bB = sb + ((t & 1) ? SM_B1 : SM_B0);

        int acc[4][4][4];
        #pragma unroll
        for (int mf = 0; mf < 4; mf++)
            #pragma unroll
            for (int nf = 0; nf < 4; nf++)
                #pragma unroll
                for (int k = 0; k < 4; k++) acc[mf][nf][k] = ACCBIAS;

        #pragma unroll
        for (int kk = 0; kk < 8; kk++) {
            uint32_t ra[4][4], rb[2][4];
            #pragma unroll
            for (int mf = 0; mf < 4; mf++) LDM4(ra[mf], aOff[mf] + kk * 32);
            #pragma unroll
            for (int h = 0; h < 2; h++)    LDM4(rb[h], bB + bOff[h] + kk * 32);
            #pragma unroll
            for (int mf = 0; mf < 4; mf++) {
                #pragma unroll
                for (int h = 0; h < 2; h++) {
                    MMAI8(acc[mf][2*h+0], ra[mf], rb[h][0], rb[h][2]);
                    MMAI8(acc[mf][2*h+1], ra[mf], rb[h][1], rb[h][3]);
                }
            }
        }

        // ---- epilogue BEFORE barrier: FFMA(bitcast, SC, OFF) + MUFU.EX2 per element ----
        const bool dg = (itC == jtC);
        float rs[8];
        #pragma unroll
        for (int i = 0; i < 8; i++) rs[i] = 0.f;

        if (!dg) {
            float cs[8];
            #pragma unroll
            for (int i = 0; i < 8; i++) cs[i] = 0.f;
            #pragma unroll
            for (int mf = 0; mf < 4; mf++)
                #pragma unroll
                for (int nf = 0; nf < 4; nf++)
                    #pragma unroll
                    for (int k = 0; k < 4; k++) {
                        float e = ex2_mufu(fmaf(__int_as_float(acc[mf][nf][k]), SCf, OFF));
                        rs[mf*2 + (k >> 1)] += e;
                        cs[nf*2 + (k & 1)] += e;
                    }
            #pragma unroll
            for (int i = 0; i < 8; i++) {
                rs[i] += __shfl_xor_sync(~0u, rs[i], 1);
                rs[i] += __shfl_xor_sync(~0u, rs[i], 2);
                cs[i] += __shfl_xor_sync(~0u, cs[i], 4);
                cs[i] += __shfl_xor_sync(~0u, cs[i], 8);
                cs[i] += __shfl_xor_sync(~0u, cs[i], 16);
            }
            if (qid == 0) {
                #pragma unroll
                for (int mf = 0; mf < 4; mf++)
                    #pragma unroll
                    for (int h = 0; h < 2; h++)
                        atomicAdd(&g_rowE[itC*TM + wm*64 + mf*16 + h*8 + grp], rs[mf*2 + h]);
            }
            if (grp == 0) {
                #pragma unroll
                for (int nf = 0; nf < 4; nf++)
                    #pragma unroll
                    for (int par = 0; par < 2; par++)
                        atomicAdd(&g_rowE[jtC*TM + wn*32 + nf*8 + 2*qid + par], cs[nf*2 + par]);
            }
        } else {
            #pragma unroll
            for (int mf = 0; mf < 4; mf++)
                #pragma unroll
                for (int nf = 0; nf < 4; nf++)
                    #pragma unroll
                    for (int k = 0; k < 4; k++) {
                        int rl = wm*64 + mf*16 + grp + (k >> 1)*8;
                        int cl = wn*32 + nf*8 + 2*qid + (k & 1);
                        if (rl != cl) {
                            float e = ex2_mufu(fmaf(__int_as_float(acc[mf][nf][k]), SCf, OFF));
                            rs[mf*2 + (k >> 1)] += e;
                        }
                    }
            #pragma unroll
            for (int i = 0; i < 8; i++) {
                rs[i] += __shfl_xor_sync(~0u, rs[i], 1);
                rs[i] += __shfl_xor_sync(~0u, rs[i], 2);
            }
            if (qid == 0) {
                #pragma unroll
                for (int mf = 0; mf < 4; mf++)
                    #pragma unroll
                    for (int h = 0; h < 2; h++)
                        atomicAdd(&g_rowE[itC*TM + wm*64 + mf*16 + h*8 + grp], rs[mf*2 + h]);
            }
        }

        __syncthreads();                           // all warps done reading smem tiles
        bool nextAFresh = false;
        if (t + 2 < cnt) cp_tile(bB, gC + (size_t)jtN2 * TILE_GM, tid);
        if (t + 1 < cnt && itN != itC) {
            cp_tile(sb + SM_A, gC + (size_t)itN * TILE_GM, tid);
            nextAFresh = true;
        }
        CP_COMMIT();

        aFresh = nextAFresh;
        itC = itN; jtC = jtN;
        itN = itN2; jtN = jtN2;
        stepPair(itN2, jtN2);
    }
}

// ================= kernel 3: finalize, 1024 threads (re-zeroes rowE) =================
__global__ void __launch_bounds__(1024) finalize_kernel(float* __restrict__ out) {
    const int tid = threadIdx.x;
    __shared__ float cbuf[1024];
    __shared__ float buf[32];

    float lsum = 0.f;
    #pragma unroll
    for (int i = tid; i < TBROWS; i += 1024) {
        lsum += logf(g_rowE[i]);
        g_rowE[i] = 0.f;
    }

    const int f = tid & 255, g4 = tid >> 8;
    float v = 0.f;
    #pragma unroll 8
    for (int bb = g4 * 128; bb < g4 * 128 + 128; bb++)
        v += g_colPart[(size_t)bb * FDIM + f];
    cbuf[tid] = v;
    __syncthreads();
    float s2 = 0.f;
    if (tid < 256) {
        float vf = cbuf[tid] + cbuf[tid + 256] + cbuf[tid + 512] + cbuf[tid + 768];
        s2 = vf * vf;
    }
    float psum = (tid < 512) ? g_posPart[tid] : 0.f;

    float vals[3] = {lsum, s2, psum};
    float tot[3];
    #pragma unroll
    for (int vv = 0; vv < 3; vv++) {
        float x = vals[vv];
        #pragma unroll
        for (int o = 16; o > 0; o >>= 1) x += __shfl_xor_sync(~0u, x, o);
        __syncthreads();
        if ((tid & 31) == 0) buf[tid >> 5] = x;
        __syncthreads();
        float r = 0.f;
        if (tid == 0) {
            #pragma unroll
            for (int i = 0; i < 32; i++) r += buf[i];
        }
        tot[vv] = r;
    }
    if (tid == 0) {
        double logSum = tot[0];
        double sSum   = (double)tot[1] - (double)TBROWS;   // sum_offdiag s
        double posSum = tot[2];
        double negMean = (10.0 * sSum - (double)(TBROWS - 1) * logSum)
                       / (4.0 * (double)BROWS * (double)BROWS);
        out[0] = (float)(-(posSum / (double)BROWS) * 10.0 + negMean);
    }
}

// ================= launch =================
extern "C" void kernel_launch(void* const* d_in, const int* in_sizes, int n_in,
                              void* d_out, int out_size) {
    const float* x1 = (const float*)d_in[0];
    const float* x2 = (const float*)d_in[1];
    float* out = (float*)d_out;

    normalize_kernel<<<512, 256>>>(x1, x2);
    cudaFuncSetAttribute(sim_kernel, cudaFuncAttributeMaxDynamicSharedMemorySize, SM_TOTAL);
    sim_kernel<<<GRID_S, 256, SM_TOTAL>>>();
    finalize_kernel<<<1, 1024>>>(out);
}